// round 1
// baseline (speedup 1.0000x reference)
#include <cuda_runtime.h>
#include <math.h>

// Problem constants
constexpr int Bc = 8;
constexpr int Sc = 4096;
constexpr int Ic = 256;
constexpr int Kc = 512;     // fan_in = WINDOW * I
constexpr int Nc = 1536;    // 2*OUT*3
constexpr int Mc = Bc * Sc; // 32768
constexpr int OUTC = 256;
constexpr int DCH = 512;    // 2*OUT

// Scan chunking
constexpr int CHUNK = 256;
constexpr int NCH = Sc / CHUNK; // 16

// Scratch: activations g (tanh(z), sigmoid(f), sigmoid(o)) in (B*S, 1536) layout
__device__ float d_g[(size_t)Mc * Nc];          // 192 MB
__device__ float d_F[Bc * NCH * DCH];           // per-chunk prod(f)
__device__ float d_C[Bc * NCH * DCH];           // per-chunk local c_end
__device__ float d_cin[Bc * NCH * DCH];         // per-chunk incoming c

// ---------------------------------------------------------------------------
// GEMM: g = A @ W^T + bias, fused activations.
// A[m][k] = x[m*256 + k - 256], zero when (k<256 && s==0). W is (1536, 512) row-major.
// ---------------------------------------------------------------------------
#define BM 128
#define BN 128
#define BK 16

struct Frag {
    float4 a[2];
    float4 b[2];
};

__device__ __forceinline__ void fetch_tiles(Frag& fr, const float* __restrict__ x,
                                            const float* __restrict__ W,
                                            int bm, int bn, int k0, int tid) {
#pragma unroll
    for (int i = 0; i < 2; i++) {
        int v = tid + i * 256;
        int row = v >> 2;            // 0..127
        int k = k0 + (v & 3) * 4;    // k within [k0, k0+16)
        int m = bm + row;
        if (k < 256 && ((m & (Sc - 1)) == 0)) {
            fr.a[i] = make_float4(0.f, 0.f, 0.f, 0.f);
        } else {
            fr.a[i] = *(const float4*)(x + (size_t)m * Ic + (k - 256));
        }
        fr.b[i] = *(const float4*)(W + (size_t)(bn + row) * Kc + k);
    }
}

__device__ __forceinline__ void store_tiles(const Frag& fr,
                                            float (*As)[BM + 4], float (*Bs)[BN + 4],
                                            int tid) {
#pragma unroll
    for (int i = 0; i < 2; i++) {
        int v = tid + i * 256;
        int row = v >> 2;
        int kq = (v & 3) * 4;
        As[kq + 0][row] = fr.a[i].x;
        As[kq + 1][row] = fr.a[i].y;
        As[kq + 2][row] = fr.a[i].z;
        As[kq + 3][row] = fr.a[i].w;
        Bs[kq + 0][row] = fr.b[i].x;
        Bs[kq + 1][row] = fr.b[i].y;
        Bs[kq + 2][row] = fr.b[i].z;
        Bs[kq + 3][row] = fr.b[i].w;
    }
}

__device__ __forceinline__ float sigm(float v) { return 1.f / (1.f + expf(-v)); }

__global__ __launch_bounds__(256) void gemm_act(const float* __restrict__ x,
                                                const float* __restrict__ W,
                                                const float* __restrict__ bias) {
    __shared__ float As[2][BK][BM + 4];
    __shared__ float Bs[2][BK][BN + 4];

    int tid = threadIdx.x;
    int bm = blockIdx.y * BM;
    int bn = blockIdx.x * BN;
    int ty = tid >> 4;   // 0..15
    int tx = tid & 15;   // 0..15

    float acc[8][8] = {};

    Frag fr;
    fetch_tiles(fr, x, W, bm, bn, 0, tid);
    store_tiles(fr, As[0], Bs[0], tid);
    __syncthreads();

    constexpr int KT = Kc / BK; // 32
    for (int kt = 0; kt < KT; kt++) {
        int cb = kt & 1;
        if (kt + 1 < KT) fetch_tiles(fr, x, W, bm, bn, (kt + 1) * BK, tid);

#pragma unroll
        for (int kk = 0; kk < BK; kk++) {
            float a[8], b[8];
#pragma unroll
            for (int i = 0; i < 8; i++) a[i] = As[cb][kk][ty * 8 + i];
#pragma unroll
            for (int j = 0; j < 8; j++) b[j] = Bs[cb][kk][tx * 8 + j];
#pragma unroll
            for (int i = 0; i < 8; i++)
#pragma unroll
                for (int j = 0; j < 8; j++) acc[i][j] = fmaf(a[i], b[j], acc[i][j]);
        }

        if (kt + 1 < KT) store_tiles(fr, As[cb ^ 1], Bs[cb ^ 1], tid);
        __syncthreads();
    }

    // Epilogue: bias + activation (whole 128-wide block is one activation type)
    bool is_z = (bn < 512); // columns 0..511 -> tanh; 512..1535 -> sigmoid
    float bcol[8];
#pragma unroll
    for (int j = 0; j < 8; j++) bcol[j] = bias[bn + tx * 8 + j];

#pragma unroll
    for (int i = 0; i < 8; i++) {
        int m = bm + ty * 8 + i;
        size_t rowoff = (size_t)m * Nc + bn;
#pragma unroll
        for (int jj = 0; jj < 2; jj++) {
            float4 vv;
            float* pv = &vv.x;
#pragma unroll
            for (int j = 0; j < 4; j++) {
                float g = acc[i][jj * 4 + j] + bcol[jj * 4 + j];
                pv[j] = is_z ? tanhf(g) : sigm(g);
            }
            *(float4*)(d_g + rowoff + tx * 8 + jj * 4) = vv;
        }
    }
}

// ---------------------------------------------------------------------------
// Scan phase 1: per-chunk local scan: F = prod(f), C = local c_end (c_in = 0).
// One thread per (b, chunk, dirch). Block = 512 threads (dirch), grid = B*NCH.
// dirch < 256: forward in time. dirch >= 256: backward in time.
// ---------------------------------------------------------------------------
__global__ __launch_bounds__(512) void scan_chunk() {
    int dirch = threadIdx.x;             // 0..511
    int b = blockIdx.x >> 4;             // / NCH
    int ck = blockIdx.x & (NCH - 1);
    bool bwd = dirch >= OUTC;
    int base = ck * CHUNK;

    float c = 0.f, F = 1.f;
#pragma unroll 8
    for (int t = 0; t < CHUNK; t++) {
        int s = bwd ? (base + CHUNK - 1 - t) : (base + t);
        size_t row = (size_t)(b * Sc + s) * Nc;
        float z = d_g[row + dirch];
        float f = d_g[row + DCH + dirch];
        c = f * c + (1.f - f) * z;
        F *= f;
    }
    int idx = (b * NCH + ck) * DCH + dirch;
    d_F[idx] = F;
    d_C[idx] = c;
}

// ---------------------------------------------------------------------------
// Scan phase 2: compose chunks per sequence. 1 thread per (b, dirch).
// ---------------------------------------------------------------------------
__global__ __launch_bounds__(512) void scan_heads() {
    int dirch = threadIdx.x;
    int b = blockIdx.x;
    bool bwd = dirch >= OUTC;

    float c = 0.f;
#pragma unroll
    for (int i = 0; i < NCH; i++) {
        int ck = bwd ? (NCH - 1 - i) : i;
        int idx = (b * NCH + ck) * DCH + dirch;
        d_cin[idx] = c;
        c = d_F[idx] * c + d_C[idx];
    }
}

// ---------------------------------------------------------------------------
// Scan phase 3: re-run local scan from c_in, gate with sigmoid(o), write out.
// ---------------------------------------------------------------------------
__global__ __launch_bounds__(512) void scan_final(float* __restrict__ out) {
    int dirch = threadIdx.x;
    int b = blockIdx.x >> 4;
    int ck = blockIdx.x & (NCH - 1);
    bool bwd = dirch >= OUTC;
    int base = ck * CHUNK;

    float c = d_cin[(b * NCH + ck) * DCH + dirch];
#pragma unroll 8
    for (int t = 0; t < CHUNK; t++) {
        int s = bwd ? (base + CHUNK - 1 - t) : (base + t);
        size_t row = (size_t)(b * Sc + s);
        const float* gr = d_g + row * Nc;
        float z = gr[dirch];
        float f = gr[DCH + dirch];
        float o = gr[2 * DCH + dirch];
        c = f * c + (1.f - f) * z;
        out[row * DCH + dirch] = o * c;
    }
}

// ---------------------------------------------------------------------------
extern "C" void kernel_launch(void* const* d_in, const int* in_sizes, int n_in,
                              void* d_out, int out_size) {
    const float* x = (const float*)d_in[0];
    const float* W = (const float*)d_in[1];
    const float* bias = (const float*)d_in[2];
    float* out = (float*)d_out;

    dim3 gg(Nc / BN, Mc / BM); // (12, 256)
    gemm_act<<<gg, 256>>>(x, W, bias);
    scan_chunk<<<Bc * NCH, 512>>>();
    scan_heads<<<Bc, 512>>>();
    scan_final<<<Bc * NCH, 512>>>(out);
}

// round 5
// speedup vs baseline: 2.3690x; 2.3690x over previous
#include <cuda_runtime.h>
#include <math.h>
#include <stdint.h>

// ---------------------------------------------------------------------------
// Problem constants
// ---------------------------------------------------------------------------
constexpr int Bc = 8;
constexpr int Sc = 4096;
constexpr int Ic = 256;
constexpr int Kc = 512;      // fan_in
constexpr int Nc = 1536;     // 2*OUT*3
constexpr int Mc = Bc * Sc;  // 32768
constexpr int OUTC = 256;
constexpr int DCH = 512;     // 2*OUT

// scan chunking
constexpr int CHUNK = 128;
constexpr int NCH = Sc / CHUNK;  // 32

// ---------------------------------------------------------------------------
// Device scratch
// ---------------------------------------------------------------------------
__device__ float d_g[(size_t)Mc * Nc];   // activated gates (192 MB)
__device__ float d_F[Bc * NCH * DCH];
__device__ float d_C[Bc * NCH * DCH];
__device__ float d_cin[Bc * NCH * DCH];

// ---------------------------------------------------------------------------
// Helpers
// ---------------------------------------------------------------------------
__device__ __forceinline__ float sigm(float v) { return 1.f / (1.f + expf(-v)); }

__device__ __forceinline__ uint32_t f2tf(float f) {
    uint32_t r;
    asm("cvt.rna.tf32.f32 %0, %1;" : "=r"(r) : "f"(f));
    return r;
}

__device__ __forceinline__ void mma_tf32(float* c, const uint32_t* a,
                                         const uint32_t* b) {
    asm volatile(
        "mma.sync.aligned.m16n8k8.row.col.f32.tf32.tf32.f32 "
        "{%0,%1,%2,%3}, {%4,%5,%6,%7}, {%8,%9}, {%0,%1,%2,%3};"
        : "+f"(c[0]), "+f"(c[1]), "+f"(c[2]), "+f"(c[3])
        : "r"(a[0]), "r"(a[1]), "r"(a[2]), "r"(a[3]), "r"(b[0]), "r"(b[1]));
}

__device__ __forceinline__ void cpasync16(uint32_t dst, const void* src,
                                          int src_bytes) {
    asm volatile("cp.async.cg.shared.global [%0], [%1], 16, %2;"
                 :: "r"(dst), "l"(src), "r"(src_bytes) : "memory");
}
__device__ __forceinline__ void cp_commit() {
    asm volatile("cp.async.commit_group;" ::: "memory");
}

// ---------------------------------------------------------------------------
// tf32 mma.sync GEMM: d_g = act(A @ W^T + bias)
// A[m][k] = x[(m-1)*256 + k]  (k in [0,512)), zeroed when s==0 && k<256.
// Tile 128x128x16, 256 threads (8 warps, 4x2), warp tile 32x64.
// Static smem: As/Bs double-buffered [128][20] floats = 40960 B.
// ---------------------------------------------------------------------------
constexpr int BM = 128;
constexpr int BN = 128;
constexpr int BK = 16;
constexpr int KP = BK + 4;      // padded row stride (floats)
constexpr int KT = Kc / BK;     // 32 k-iterations

__global__ __launch_bounds__(256) void gemm_mma(const float* __restrict__ x,
                                                const float* __restrict__ W,
                                                const float* __restrict__ bias) {
    __shared__ float As[2][BM][KP];
    __shared__ float Bs[2][BN][KP];

    const int tid = threadIdx.x;
    const int warp = tid >> 5, lane = tid & 31;
    const int g = lane >> 2, t = lane & 3;
    const int wm = (warp >> 1) * 32;   // warp M offset in tile
    const int wn = (warp & 1) * 64;    // warp N offset in tile
    const int bm = blockIdx.y * BM;
    const int bn = blockIdx.x * BN;

    float acc[2][8][4];
#pragma unroll
    for (int i = 0; i < 2; i++)
#pragma unroll
        for (int j = 0; j < 8; j++)
#pragma unroll
            for (int q = 0; q < 4; q++) acc[i][j][q] = 0.f;

    uint32_t sbA = (uint32_t)__cvta_generic_to_shared(&As[0][0][0]);
    uint32_t sbB = (uint32_t)__cvta_generic_to_shared(&Bs[0][0][0]);

    // stage loader: 512 16B-chunks per operand tile, 2 per thread each
    auto load_stage = [&](int st, int kt) {
        int k0 = kt * BK;
#pragma unroll
        for (int i = 0; i < 2; i++) {
            int id = tid + i * 256;          // 0..511
            int row = id >> 2, c = id & 3;   // row 0..127, 16B chunk 0..3
            int m = bm + row;
            int kk = k0 + c * 4;
            // A
            {
                bool zero = ((m & (Sc - 1)) == 0) && (kk < 256);
                const float* src = zero ? x : (x + (size_t)(m - 1) * Ic + kk);
                cpasync16(sbA + (uint32_t)(st * BM * KP + row * KP + c * 4) * 4,
                          src, zero ? 0 : 16);
            }
            // B
            {
                const float* src = W + (size_t)(bn + row) * Kc + kk;
                cpasync16(sbB + (uint32_t)(st * BN * KP + row * KP + c * 4) * 4,
                          src, 16);
            }
        }
        cp_commit();
    };

    load_stage(0, 0);

    for (int kt = 0; kt < KT; kt++) {
        int st = kt & 1;
        if (kt + 1 < KT) {
            load_stage(st ^ 1, kt + 1);
            asm volatile("cp.async.wait_group 1;" ::: "memory");
        } else {
            asm volatile("cp.async.wait_group 0;" ::: "memory");
        }
        __syncthreads();

#pragma unroll
        for (int ks = 0; ks < 2; ks++) {
            int kb = ks * 8;
            uint32_t a[2][4], b[8][2];
#pragma unroll
            for (int i = 0; i < 2; i++) {
                int r0 = wm + i * 16;
                a[i][0] = f2tf(As[st][r0 + g][kb + t]);
                a[i][1] = f2tf(As[st][r0 + g + 8][kb + t]);
                a[i][2] = f2tf(As[st][r0 + g][kb + t + 4]);
                a[i][3] = f2tf(As[st][r0 + g + 8][kb + t + 4]);
            }
#pragma unroll
            for (int j = 0; j < 8; j++) {
                int n0 = wn + j * 8;
                b[j][0] = f2tf(Bs[st][n0 + g][kb + t]);
                b[j][1] = f2tf(Bs[st][n0 + g][kb + t + 4]);
            }
#pragma unroll
            for (int i = 0; i < 2; i++)
#pragma unroll
                for (int j = 0; j < 8; j++) mma_tf32(acc[i][j], a[i], b[j]);
        }
        __syncthreads();
    }

    // Epilogue: bias + activation, float2 stores
    const bool is_z = (bn < 512);  // cols [0,512) tanh; else sigmoid
#pragma unroll
    for (int i = 0; i < 2; i++) {
#pragma unroll
        for (int j = 0; j < 8; j++) {
            int col = bn + wn + j * 8 + 2 * t;
            float b0 = __ldg(bias + col), b1 = __ldg(bias + col + 1);
            int r0 = bm + wm + i * 16 + g;
            float2 v;
            v.x = acc[i][j][0] + b0;
            v.y = acc[i][j][1] + b1;
            v.x = is_z ? tanhf(v.x) : sigm(v.x);
            v.y = is_z ? tanhf(v.y) : sigm(v.y);
            *(float2*)(d_g + (size_t)r0 * Nc + col) = v;
            v.x = acc[i][j][2] + b0;
            v.y = acc[i][j][3] + b1;
            v.x = is_z ? tanhf(v.x) : sigm(v.x);
            v.y = is_z ? tanhf(v.y) : sigm(v.y);
            *(float2*)(d_g + (size_t)(r0 + 8) * Nc + col) = v;
        }
    }
}

// ---------------------------------------------------------------------------
// Scans (chunk-parallel linear recurrence)
// ---------------------------------------------------------------------------
__global__ __launch_bounds__(512) void scan_chunk() {
    int dirch = threadIdx.x;
    int b = blockIdx.x >> 5;
    int ck = blockIdx.x & (NCH - 1);
    bool bwd = dirch >= OUTC;
    int base = ck * CHUNK;

    float c = 0.f, F = 1.f;
#pragma unroll 8
    for (int t = 0; t < CHUNK; t++) {
        int s = bwd ? (base + CHUNK - 1 - t) : (base + t);
        size_t row = (size_t)(b * Sc + s) * Nc;
        float z = d_g[row + dirch];
        float f = d_g[row + DCH + dirch];
        c = f * c + (1.f - f) * z;
        F *= f;
    }
    int idx = (b * NCH + ck) * DCH + dirch;
    d_F[idx] = F;
    d_C[idx] = c;
}

__global__ __launch_bounds__(512) void scan_heads() {
    int dirch = threadIdx.x;
    int b = blockIdx.x;
    bool bwd = dirch >= OUTC;

    float c = 0.f;
#pragma unroll
    for (int i = 0; i < NCH; i++) {
        int ck = bwd ? (NCH - 1 - i) : i;
        int idx = (b * NCH + ck) * DCH + dirch;
        d_cin[idx] = c;
        c = d_F[idx] * c + d_C[idx];
    }
}

__global__ __launch_bounds__(512) void scan_final(float* __restrict__ out) {
    int dirch = threadIdx.x;
    int b = blockIdx.x >> 5;
    int ck = blockIdx.x & (NCH - 1);
    bool bwd = dirch >= OUTC;
    int base = ck * CHUNK;

    float c = d_cin[(b * NCH + ck) * DCH + dirch];
#pragma unroll 8
    for (int t = 0; t < CHUNK; t++) {
        int s = bwd ? (base + CHUNK - 1 - t) : (base + t);
        size_t row = (size_t)(b * Sc + s);
        const float* gr = d_g + row * Nc;
        float z = gr[dirch];
        float f = gr[DCH + dirch];
        float o = gr[2 * DCH + dirch];
        c = f * c + (1.f - f) * z;
        out[row * DCH + dirch] = o * c;
    }
}

// ---------------------------------------------------------------------------
extern "C" void kernel_launch(void* const* d_in, const int* in_sizes, int n_in,
                              void* d_out, int out_size) {
    const float* x = (const float*)d_in[0];
    const float* W = (const float*)d_in[1];
    const float* bias = (const float*)d_in[2];
    float* out = (float*)d_out;

    dim3 gg(Nc / BN, Mc / BM);  // (12, 256)
    gemm_mma<<<gg, 256>>>(x, W, bias);

    scan_chunk<<<Bc * NCH, 512>>>();
    scan_heads<<<Bc, 512>>>();
    scan_final<<<Bc * NCH, 512>>>(out);
}

// round 7
// speedup vs baseline: 2.5250x; 1.0659x over previous
#include <cuda_runtime.h>
#include <math.h>
#include <stdint.h>

// ---------------------------------------------------------------------------
// Problem constants
// ---------------------------------------------------------------------------
constexpr int Bc = 8;
constexpr int Sc = 4096;
constexpr int Ic = 256;
constexpr int Kc = 512;      // fan_in
constexpr int Nc = 1536;     // 2*OUT*3
constexpr int Mc = Bc * Sc;  // 32768
constexpr int OUTC = 256;
constexpr int DCH = 512;     // 2*OUT

// scan chunking
constexpr int CHUNK = 64;
constexpr int NCH = Sc / CHUNK;  // 64

// ---------------------------------------------------------------------------
// Device scratch
// ---------------------------------------------------------------------------
__device__ float d_g[(size_t)Mc * Nc];     // activated gates (192 MB)
__device__ float d_xr[(size_t)Mc * Ic];    // tf32-rounded x (33.5 MB)
__device__ float d_wr[(size_t)Nc * Kc];    // tf32-rounded W (3 MB)
__device__ float d_F[Bc * NCH * DCH];
__device__ float d_C[Bc * NCH * DCH];
__device__ float d_cin[Bc * NCH * DCH];

// ---------------------------------------------------------------------------
// Helpers
// ---------------------------------------------------------------------------
__device__ __forceinline__ float sigm(float v) { return 1.f / (1.f + expf(-v)); }

__device__ __forceinline__ float f2tf_f(float f) {
    uint32_t r;
    asm("cvt.rna.tf32.f32 %0, %1;" : "=r"(r) : "f"(f));
    return __uint_as_float(r);
}

__device__ __forceinline__ void mma_tf32(float* c, const uint32_t* a,
                                         const uint32_t* b) {
    asm volatile(
        "mma.sync.aligned.m16n8k8.row.col.f32.tf32.tf32.f32 "
        "{%0,%1,%2,%3}, {%4,%5,%6,%7}, {%8,%9}, {%0,%1,%2,%3};"
        : "+f"(c[0]), "+f"(c[1]), "+f"(c[2]), "+f"(c[3])
        : "r"(a[0]), "r"(a[1]), "r"(a[2]), "r"(a[3]), "r"(b[0]), "r"(b[1]));
}

__device__ __forceinline__ void cpasync16(uint32_t dst, const void* src,
                                          int src_bytes) {
    asm volatile("cp.async.cg.shared.global [%0], [%1], 16, %2;"
                 :: "r"(dst), "l"(src), "r"(src_bytes) : "memory");
}
__device__ __forceinline__ void cp_commit() {
    asm volatile("cp.async.commit_group;" ::: "memory");
}

// ---------------------------------------------------------------------------
// Pre-round inputs to tf32 (rne) stored as fp32 bits. float4 vectorized.
// ---------------------------------------------------------------------------
__global__ __launch_bounds__(256) void round_x(const float* __restrict__ x) {
    size_t i = ((size_t)blockIdx.x * 256 + threadIdx.x) * 4;
    float4 v = *(const float4*)(x + i);
    v.x = f2tf_f(v.x); v.y = f2tf_f(v.y); v.z = f2tf_f(v.z); v.w = f2tf_f(v.w);
    *(float4*)(d_xr + i) = v;
}

__global__ __launch_bounds__(256) void round_w(const float* __restrict__ W) {
    size_t i = ((size_t)blockIdx.x * 256 + threadIdx.x) * 4;
    float4 v = *(const float4*)(W + i);
    v.x = f2tf_f(v.x); v.y = f2tf_f(v.y); v.z = f2tf_f(v.z); v.w = f2tf_f(v.w);
    *(float4*)(d_wr + i) = v;
}

// ---------------------------------------------------------------------------
// tf32 mma.sync GEMM: d_g = act(A @ W^T + bias)
// A[m][k] = xr[(m-1)*256 + k]  (k in [0,512)), zeroed when s==0 && k<256.
// Tile 128x128x16, 256 threads (8 warps, 4x2), warp tile 32x64.
// Static smem: As/Bs double-buffered [128][20] floats = 40960 B.
// Operands already tf32-rounded -> no cvt in the inner loop.
// ---------------------------------------------------------------------------
constexpr int BM = 128;
constexpr int BN = 128;
constexpr int BK = 16;
constexpr int KP = BK + 4;      // padded row stride (floats)
constexpr int KT = Kc / BK;     // 32 k-iterations

__global__ __launch_bounds__(256) void gemm_mma(const float* __restrict__ bias) {
    __shared__ float As[2][BM][KP];
    __shared__ float Bs[2][BN][KP];

    const int tid = threadIdx.x;
    const int warp = tid >> 5, lane = tid & 31;
    const int g = lane >> 2, t = lane & 3;
    const int wm = (warp >> 1) * 32;   // warp M offset in tile
    const int wn = (warp & 1) * 64;    // warp N offset in tile
    const int bm = blockIdx.y * BM;
    const int bn = blockIdx.x * BN;

    float acc[2][8][4];
#pragma unroll
    for (int i = 0; i < 2; i++)
#pragma unroll
        for (int j = 0; j < 8; j++)
#pragma unroll
            for (int q = 0; q < 4; q++) acc[i][j][q] = 0.f;

    uint32_t sbA = (uint32_t)__cvta_generic_to_shared(&As[0][0][0]);
    uint32_t sbB = (uint32_t)__cvta_generic_to_shared(&Bs[0][0][0]);

    auto load_stage = [&](int st, int kt) {
        int k0 = kt * BK;
#pragma unroll
        for (int i = 0; i < 2; i++) {
            int id = tid + i * 256;          // 0..511
            int row = id >> 2, c = id & 3;   // row 0..127, 16B chunk 0..3
            int m = bm + row;
            int kk = k0 + c * 4;
            {
                bool zero = ((m & (Sc - 1)) == 0) && (kk < 256);
                const float* src = zero ? d_xr : (d_xr + (size_t)(m - 1) * Ic + kk);
                cpasync16(sbA + (uint32_t)(st * BM * KP + row * KP + c * 4) * 4,
                          src, zero ? 0 : 16);
            }
            {
                const float* src = d_wr + (size_t)(bn + row) * Kc + kk;
                cpasync16(sbB + (uint32_t)(st * BN * KP + row * KP + c * 4) * 4,
                          src, 16);
            }
        }
        cp_commit();
    };

    load_stage(0, 0);

    for (int kt = 0; kt < KT; kt++) {
        int st = kt & 1;
        if (kt + 1 < KT) {
            load_stage(st ^ 1, kt + 1);
            asm volatile("cp.async.wait_group 1;" ::: "memory");
        } else {
            asm volatile("cp.async.wait_group 0;" ::: "memory");
        }
        __syncthreads();

#pragma unroll
        for (int ks = 0; ks < 2; ks++) {
            int kb = ks * 8;
            uint32_t a[2][4], b[8][2];
#pragma unroll
            for (int i = 0; i < 2; i++) {
                int r0 = wm + i * 16;
                a[i][0] = __float_as_uint(As[st][r0 + g][kb + t]);
                a[i][1] = __float_as_uint(As[st][r0 + g + 8][kb + t]);
                a[i][2] = __float_as_uint(As[st][r0 + g][kb + t + 4]);
                a[i][3] = __float_as_uint(As[st][r0 + g + 8][kb + t + 4]);
            }
#pragma unroll
            for (int j = 0; j < 8; j++) {
                int n0 = wn + j * 8;
                b[j][0] = __float_as_uint(Bs[st][n0 + g][kb + t]);
                b[j][1] = __float_as_uint(Bs[st][n0 + g][kb + t + 4]);
            }
#pragma unroll
            for (int i = 0; i < 2; i++)
#pragma unroll
                for (int j = 0; j < 8; j++) mma_tf32(acc[i][j], a[i], b[j]);
        }
        __syncthreads();
    }

    // Epilogue: bias + activation, float2 stores
    const bool is_z = (bn < 512);  // cols [0,512) tanh; else sigmoid
#pragma unroll
    for (int i = 0; i < 2; i++) {
#pragma unroll
        for (int j = 0; j < 8; j++) {
            int col = bn + wn + j * 8 + 2 * t;
            float b0 = __ldg(bias + col), b1 = __ldg(bias + col + 1);
            int r0 = bm + wm + i * 16 + g;
            float2 v;
            v.x = acc[i][j][0] + b0;
            v.y = acc[i][j][1] + b1;
            v.x = is_z ? tanhf(v.x) : sigm(v.x);
            v.y = is_z ? tanhf(v.y) : sigm(v.y);
            *(float2*)(d_g + (size_t)r0 * Nc + col) = v;
            v.x = acc[i][j][2] + b0;
            v.y = acc[i][j][3] + b1;
            v.x = is_z ? tanhf(v.x) : sigm(v.x);
            v.y = is_z ? tanhf(v.y) : sigm(v.y);
            *(float2*)(d_g + (size_t)(r0 + 8) * Nc + col) = v;
        }
    }
}

// ---------------------------------------------------------------------------
// Scans (chunk-parallel linear recurrence), CHUNK=64 for occupancy
// ---------------------------------------------------------------------------
__global__ __launch_bounds__(512) void scan_chunk() {
    int dirch = threadIdx.x;
    int b = blockIdx.x >> 6;
    int ck = blockIdx.x & (NCH - 1);
    bool bwd = dirch >= OUTC;
    int base = ck * CHUNK;

    float c = 0.f, F = 1.f;
#pragma unroll 8
    for (int t = 0; t < CHUNK; t++) {
        int s = bwd ? (base + CHUNK - 1 - t) : (base + t);
        size_t row = (size_t)(b * Sc + s) * Nc;
        float z = d_g[row + dirch];
        float f = d_g[row + DCH + dirch];
        c = f * c + (1.f - f) * z;
        F *= f;
    }
    int idx = (b * NCH + ck) * DCH + dirch;
    d_F[idx] = F;
    d_C[idx] = c;
}

__global__ __launch_bounds__(512) void scan_heads() {
    int dirch = threadIdx.x;
    int b = blockIdx.x;
    bool bwd = dirch >= OUTC;

    float c = 0.f;
#pragma unroll
    for (int i = 0; i < NCH; i++) {
        int ck = bwd ? (NCH - 1 - i) : i;
        int idx = (b * NCH + ck) * DCH + dirch;
        d_cin[idx] = c;
        c = d_F[idx] * c + d_C[idx];
    }
}

__global__ __launch_bounds__(512) void scan_final(float* __restrict__ out) {
    int dirch = threadIdx.x;
    int b = blockIdx.x >> 6;
    int ck = blockIdx.x & (NCH - 1);
    bool bwd = dirch >= OUTC;
    int base = ck * CHUNK;

    float c = d_cin[(b * NCH + ck) * DCH + dirch];
#pragma unroll 8
    for (int t = 0; t < CHUNK; t++) {
        int s = bwd ? (base + CHUNK - 1 - t) : (base + t);
        size_t row = (size_t)(b * Sc + s);
        const float* gr = d_g + row * Nc;
        float z = gr[dirch];
        float f = gr[DCH + dirch];
        float o = gr[2 * DCH + dirch];
        c = f * c + (1.f - f) * z;
        out[row * DCH + dirch] = o * c;
    }
}

// ---------------------------------------------------------------------------
extern "C" void kernel_launch(void* const* d_in, const int* in_sizes, int n_in,
                              void* d_out, int out_size) {
    const float* x = (const float*)d_in[0];
    const float* W = (const float*)d_in[1];
    const float* bias = (const float*)d_in[2];
    float* out = (float*)d_out;

    round_x<<<(Mc * Ic) / (256 * 4), 256>>>(x);       // 8192 blocks
    round_w<<<(Nc * Kc) / (256 * 4), 256>>>(W);       // 768 blocks

    dim3 gg(Nc / BN, Mc / BM);  // (12, 256)
    gemm_mma<<<gg, 256>>>(bias);

    scan_chunk<<<Bc * NCH, 512>>>();
    scan_heads<<<Bc, 512>>>();
    scan_final<<<Bc * NCH, 512>>>(out);
}